// round 2
// baseline (speedup 1.0000x reference)
#include <cuda_runtime.h>
#include <math.h>

#define Bsz 64
#define Ssz 64
#define Tsz 32
#define Vsz 32000
#define Esz 256
#define Hsz 512
#define G3H (3*Hsz)   // 1536

// ---------------- scratch (static device globals; no runtime allocation) ----
__device__ float g_gx_enc[Bsz*Ssz*G3H];  // [b*S + t][1536] precomputed x@Wx+b
__device__ float g_gxd[Bsz*G3H];         // decoder per-step x@Wx+b
__device__ float g_h[Bsz*Hsz];           // hidden state
__device__ float g_z[Bsz*Hsz];           // z gate
__device__ float g_rh[Bsz*Hsz];          // r*h
__device__ float g_logits[Bsz*Vsz];      // decoder logits
__device__ int   g_tok[Bsz];             // argmax feedback token
__device__ float g_ce[Bsz];              // per-row accumulated masked CE

__global__ void init_kernel() {
    int tid = threadIdx.x;
    for (int i = tid; i < Bsz*Hsz; i += blockDim.x) g_h[i] = 0.f;
    if (tid < Bsz) { g_ce[tid] = 0.f; g_tok[tid] = 1; /* BEGIN */ }
}

// ---------------------------------------------------------------------------
// Tiled fp32 GEMM with fused GRU epilogues.
// MODE 0: C = acc (+bias), C selected by c_sel (0=g_gx_enc, 1=g_gxd, 2=g_logits)
// MODE 1: zr gate: s = sigmoid(gx[n] + acc); n<512 -> g_z, else g_rh = s*h
// MODE 2: hh gate: hh = tanh(gx[1024+n] + acc); g_h = z*h + (1-z)*hh
// a_kind: 0 = Aext rows gathered via ridx; 1 = Aext gathered via g_tok;
//         2 = g_h; 3 = g_rh
// ---------------------------------------------------------------------------
template<int MODE, int BM, int BN, int BK, int TM, int TN>
__global__ void gemm_k(const float* __restrict__ Aext, const int* __restrict__ ridx,
                       int a_kind, int lda,
                       const float* __restrict__ Bp, int ldb,
                       const float* __restrict__ bias,
                       int c_sel, int ldc,
                       int gx_sel, int tstep,
                       int K)
{
    constexpr int NT = (BM/TM)*(BN/TN);   // must equal blockDim.x (256)
    __shared__ float As[BK][BM+1];
    __shared__ float Bs[BK][BN+4];
    const int n0 = blockIdx.x * BN;
    const int m0 = blockIdx.y * BM;
    const int tid = threadIdx.x;
    const int tx = tid % (BN/TN);
    const int ty = tid / (BN/TN);

    float acc[TM][TN];
    #pragma unroll
    for (int i = 0; i < TM; i++)
        #pragma unroll
        for (int j = 0; j < TN; j++) acc[i][j] = 0.f;

    for (int k0 = 0; k0 < K; k0 += BK) {
        // ---- load A tile (BM x BK) ----
        #pragma unroll
        for (int p = 0; p < (BM*BK)/NT; p++) {
            int idx = tid + p*NT;
            int am = idx / BK, ak = idx % BK;
            int m = m0 + am;
            const float* arow;
            if (a_kind == 0)      arow = Aext + (size_t)ridx[m]  * lda;
            else if (a_kind == 1) arow = Aext + (size_t)g_tok[m] * lda;
            else if (a_kind == 2) arow = g_h  + (size_t)m * lda;
            else                  arow = g_rh + (size_t)m * lda;
            As[ak][am] = arow[k0 + ak];
        }
        // ---- load B tile (BK x BN) ----
        #pragma unroll
        for (int p = 0; p < (BK*BN)/NT; p++) {
            int idx = tid + p*NT;
            int bk = idx / BN, bn = idx % BN;
            Bs[bk][bn] = Bp[(size_t)(k0 + bk) * ldb + n0 + bn];
        }
        __syncthreads();
        // ---- compute ----
        #pragma unroll
        for (int k = 0; k < BK; k++) {
            float av[TM], bv[TN];
            #pragma unroll
            for (int i = 0; i < TM; i++) av[i] = As[k][ty*TM + i];
            #pragma unroll
            for (int j = 0; j < TN; j++) bv[j] = Bs[k][tx*TN + j];
            #pragma unroll
            for (int i = 0; i < TM; i++)
                #pragma unroll
                for (int j = 0; j < TN; j++)
                    acc[i][j] += av[i] * bv[j];
        }
        __syncthreads();
    }

    // ---- epilogue ----
    #pragma unroll
    for (int i = 0; i < TM; i++) {
        #pragma unroll
        for (int j = 0; j < TN; j++) {
            int m = m0 + ty*TM + i;
            int n = n0 + tx*TN + j;
            float v = acc[i][j];
            if (MODE == 0) {
                if (bias) v += bias[n];
                float* C = (c_sel == 0) ? g_gx_enc : (c_sel == 1 ? g_gxd : g_logits);
                C[(size_t)m * ldc + n] = v;
            } else {
                const float* gxb = gx_sel ? g_gxd : (g_gx_enc + (size_t)tstep * G3H);
                const int gxs = gx_sel ? G3H : Ssz * G3H;
                if (MODE == 1) {
                    float s = 1.f / (1.f + expf(-(gxb[(size_t)m*gxs + n] + v)));
                    if (n < Hsz) g_z[m*Hsz + n] = s;
                    else         g_rh[m*Hsz + n - Hsz] = s * g_h[m*Hsz + n - Hsz];
                } else {
                    float hh = tanhf(gxb[(size_t)m*gxs + 2*Hsz + n] + v);
                    float z = g_z[m*Hsz + n], hp = g_h[m*Hsz + n];
                    g_h[m*Hsz + n] = z*hp + (1.f - z)*hh;
                }
            }
        }
    }
}

// ---------------------------------------------------------------------------
// Per-row (b) softmax + double-softmax CE + argmax feedback.
// preds = softmax(logits); ce = logsumexp(preds) - preds[tgt]; tok = argmax.
// Deterministic: each block owns its row's g_ce[b].
// ---------------------------------------------------------------------------
__global__ void softmax_loss_kernel(const int* __restrict__ targ, int tcol)
{
    __shared__ float s_f[256];
    __shared__ int   s_i[256];
    int b = blockIdx.x, tid = threadIdx.x;
    const float* row = g_logits + (size_t)b * Vsz;

    // pass 1: max + first-occurrence argmax
    float bv = -1e30f; int bi = 0;
    for (int n = tid; n < Vsz; n += 256) {
        float l = row[n];
        if (l > bv) { bv = l; bi = n; }
    }
    s_f[tid] = bv; s_i[tid] = bi;
    __syncthreads();
    for (int st = 128; st > 0; st >>= 1) {
        if (tid < st) {
            float v2 = s_f[tid+st]; int i2 = s_i[tid+st];
            if (v2 > s_f[tid] || (v2 == s_f[tid] && i2 < s_i[tid])) {
                s_f[tid] = v2; s_i[tid] = i2;
            }
        }
        __syncthreads();
    }
    float M = s_f[0]; int amax = s_i[0];
    __syncthreads();

    // pass 2: Z = sum exp(l - M)
    float Z = 0.f;
    for (int n = tid; n < Vsz; n += 256) Z += expf(row[n] - M);
    s_f[tid] = Z; __syncthreads();
    for (int st = 128; st > 0; st >>= 1) {
        if (tid < st) s_f[tid] += s_f[tid+st];
        __syncthreads();
    }
    float Zt = s_f[0];
    __syncthreads();

    // pass 3: S2 = sum exp(preds)
    float S2 = 0.f;
    for (int n = tid; n < Vsz; n += 256) S2 += expf(expf(row[n] - M) / Zt);
    s_f[tid] = S2; __syncthreads();
    for (int st = 128; st > 0; st >>= 1) {
        if (tid < st) s_f[tid] += s_f[tid+st];
        __syncthreads();
    }

    if (tid == 0) {
        int tg = targ[b*Tsz + tcol];
        float pt = expf(row[tg] - M) / Zt;
        float ce = logf(s_f[0]) - pt;          // lse(preds) - preds[tgt]
        if (tg != 0) g_ce[b] += ce;
        g_tok[b] = amax;
    }
}

__global__ void final_kernel(float* __restrict__ out)
{
    __shared__ float s[64];
    int tid = threadIdx.x;
    s[tid] = g_ce[tid];
    __syncthreads();
    for (int st = 32; st > 0; st >>= 1) {
        if (tid < st) s[tid] += s[tid+st];
        __syncthreads();
    }
    if (tid == 0) out[0] = s[0] * (1.0f / 64.0f);
}

// ---------------------------------------------------------------------------
extern "C" void kernel_launch(void* const* d_in, const int* in_sizes, int n_in,
                              void* d_out, int out_size)
{
    const int*   inp     = (const int*)  d_in[0];
    const int*   targ    = (const int*)  d_in[1];
    const float* emb_enc = (const float*)d_in[2];
    const float* enc_Wx  = (const float*)d_in[3];
    const float* enc_Wh  = (const float*)d_in[4];
    const float* enc_b   = (const float*)d_in[5];
    const float* emb_dec = (const float*)d_in[6];
    const float* dec_Wx  = (const float*)d_in[7];
    const float* dec_Wh  = (const float*)d_in[8];
    const float* dec_b   = (const float*)d_in[9];
    const float* fc_W    = (const float*)d_in[10];
    const float* fc_b    = (const float*)d_in[11];
    float* out = (float*)d_out;

    init_kernel<<<1, 256>>>();

    // Encoder input projection for all 64 steps at once:
    // g_gx_enc[b*S+t] = emb_enc[inp[b,t]] @ enc_Wx + enc_b
    {
        dim3 g(G3H/64, (Bsz*Ssz)/64);
        gemm_k<0,64,64,16,4,4><<<g, 256>>>(emb_enc, inp, /*a_kind*/0, Esz,
                                           enc_Wx, G3H, enc_b, /*c_sel*/0, G3H,
                                           0, 0, Esz);
    }

    // Encoder recurrence
    for (int t = 0; t < Ssz; t++) {
        dim3 gz((2*Hsz)/64, Bsz/16);
        gemm_k<1,16,64,32,1,4><<<gz, 256>>>(nullptr, nullptr, 2, Hsz,
                                            enc_Wh, G3H, nullptr, 0, 0,
                                            /*gx_sel*/0, t, Hsz);
        dim3 gh(Hsz/64, Bsz/16);
        gemm_k<2,16,64,32,1,4><<<gh, 256>>>(nullptr, nullptr, 3, Hsz,
                                            enc_Wh + 2*Hsz, G3H, nullptr, 0, 0,
                                            /*gx_sel*/0, t, Hsz);
    }

    // Decoder: greedy loop over targ[:, 1..31]
    for (int s = 0; s < Tsz - 1; s++) {
        // gx = emb_dec[tok] @ dec_Wx + dec_b
        dim3 gg(G3H/64, Bsz/16);
        gemm_k<0,16,64,32,1,4><<<gg, 256>>>(emb_dec, nullptr, /*a_kind*/1, Esz,
                                            dec_Wx, G3H, dec_b, /*c_sel*/1, G3H,
                                            0, 0, Esz);
        dim3 gz((2*Hsz)/64, Bsz/16);
        gemm_k<1,16,64,32,1,4><<<gz, 256>>>(nullptr, nullptr, 2, Hsz,
                                            dec_Wh, G3H, nullptr, 0, 0,
                                            /*gx_sel*/1, 0, Hsz);
        dim3 gh(Hsz/64, Bsz/16);
        gemm_k<2,16,64,32,1,4><<<gh, 256>>>(nullptr, nullptr, 3, Hsz,
                                            dec_Wh + 2*Hsz, G3H, nullptr, 0, 0,
                                            /*gx_sel*/1, 0, Hsz);
        // logits = h @ fc_W + fc_b
        dim3 gf(Vsz/64, Bsz/64);
        gemm_k<0,64,64,16,4,4><<<gf, 256>>>(nullptr, nullptr, /*a_kind*/2, Hsz,
                                            fc_W, Vsz, fc_b, /*c_sel*/2, Vsz,
                                            0, 0, Hsz);
        softmax_loss_kernel<<<Bsz, 256>>>(targ, s + 1);
    }

    final_kernel<<<1, 64>>>(out);
}

// round 3
// speedup vs baseline: 1.0056x; 1.0056x over previous
#include <cuda_runtime.h>
#include <math.h>

#define Bsz 64
#define Ssz 64
#define Tsz 32
#define Vsz 32000
#define Esz 256
#define Hsz 512
#define G3H (3*Hsz)   // 1536

// ---------------- scratch (static device globals; no runtime allocation) ----
__device__ float g_gx_enc[Bsz*Ssz*G3H];  // [b*S + t][1536] precomputed x@Wx+b
__device__ float g_gxd[Bsz*G3H];         // decoder per-step x@Wx+b
__device__ float g_h[Bsz*Hsz];           // hidden state
__device__ float g_z[Bsz*Hsz];           // z gate
__device__ float g_rh[Bsz*Hsz];          // r*h
__device__ float g_logits[Bsz*Vsz];      // decoder logits
__device__ int   g_tok[Bsz];             // argmax feedback token
__device__ float g_ce[Bsz];              // per-row accumulated masked CE

__global__ void init_kernel() {
    int tid = threadIdx.x;
    for (int i = tid; i < Bsz*Hsz; i += blockDim.x) g_h[i] = 0.f;
    if (tid < Bsz) { g_ce[tid] = 0.f; g_tok[tid] = 1; /* BEGIN */ }
}

// ---------------------------------------------------------------------------
// Tiled fp32 GEMM with fused GRU epilogues.
// MODE 0: C = acc (+bias), C selected by c_sel (0=g_gx_enc, 1=g_gxd, 2=g_logits)
// MODE 1: zr gate: s = sigmoid(gx[n] + acc); n<512 -> g_z, else g_rh = s*h
// MODE 2: hh gate: hh = tanh(gx[1024+n] + acc); g_h = z*h + (1-z)*hh
// a_kind: 0 = Aext rows gathered via ridx; 1 = Aext gathered via g_tok;
//         2 = g_h; 3 = g_rh
// ---------------------------------------------------------------------------
template<int MODE, int BM, int BN, int BK, int TM, int TN>
__global__ void gemm_k(const float* __restrict__ Aext, const int* __restrict__ ridx,
                       int a_kind, int lda,
                       const float* __restrict__ Bp, int ldb,
                       const float* __restrict__ bias,
                       int c_sel, int ldc,
                       int gx_sel, int tstep,
                       int K)
{
    constexpr int NT = (BM/TM)*(BN/TN);   // must equal blockDim.x (256)
    __shared__ float As[BK][BM+1];
    __shared__ float Bs[BK][BN+4];
    const int n0 = blockIdx.x * BN;
    const int m0 = blockIdx.y * BM;
    const int tid = threadIdx.x;
    const int tx = tid % (BN/TN);
    const int ty = tid / (BN/TN);

    float acc[TM][TN];
    #pragma unroll
    for (int i = 0; i < TM; i++)
        #pragma unroll
        for (int j = 0; j < TN; j++) acc[i][j] = 0.f;

    for (int k0 = 0; k0 < K; k0 += BK) {
        // ---- load A tile (BM x BK) ----
        #pragma unroll
        for (int p = 0; p < (BM*BK)/NT; p++) {
            int idx = tid + p*NT;
            int am = idx / BK, ak = idx % BK;
            int m = m0 + am;
            const float* arow;
            if (a_kind == 0)      arow = Aext + (size_t)ridx[m]  * lda;
            else if (a_kind == 1) arow = Aext + (size_t)g_tok[m] * lda;
            else if (a_kind == 2) arow = g_h  + (size_t)m * lda;
            else                  arow = g_rh + (size_t)m * lda;
            As[ak][am] = arow[k0 + ak];
        }
        // ---- load B tile (BK x BN) ----
        #pragma unroll
        for (int p = 0; p < (BK*BN)/NT; p++) {
            int idx = tid + p*NT;
            int bk = idx / BN, bn = idx % BN;
            Bs[bk][bn] = Bp[(size_t)(k0 + bk) * ldb + n0 + bn];
        }
        __syncthreads();
        // ---- compute ----
        #pragma unroll
        for (int k = 0; k < BK; k++) {
            float av[TM], bv[TN];
            #pragma unroll
            for (int i = 0; i < TM; i++) av[i] = As[k][ty*TM + i];
            #pragma unroll
            for (int j = 0; j < TN; j++) bv[j] = Bs[k][tx*TN + j];
            #pragma unroll
            for (int i = 0; i < TM; i++)
                #pragma unroll
                for (int j = 0; j < TN; j++)
                    acc[i][j] += av[i] * bv[j];
        }
        __syncthreads();
    }

    // ---- epilogue ----
    #pragma unroll
    for (int i = 0; i < TM; i++) {
        #pragma unroll
        for (int j = 0; j < TN; j++) {
            int m = m0 + ty*TM + i;
            int n = n0 + tx*TN + j;
            float v = acc[i][j];
            if (MODE == 0) {
                if (bias) v += bias[n];
                float* C = (c_sel == 0) ? g_gx_enc : (c_sel == 1 ? g_gxd : g_logits);
                C[(size_t)m * ldc + n] = v;
            } else {
                const float* gxb = gx_sel ? g_gxd : (g_gx_enc + (size_t)tstep * G3H);
                const int gxs = gx_sel ? G3H : Ssz * G3H;
                if (MODE == 1) {
                    float s = 1.f / (1.f + expf(-(gxb[(size_t)m*gxs + n] + v)));
                    if (n < Hsz) g_z[m*Hsz + n] = s;
                    else         g_rh[m*Hsz + n - Hsz] = s * g_h[m*Hsz + n - Hsz];
                } else {
                    float hh = tanhf(gxb[(size_t)m*gxs + 2*Hsz + n] + v);
                    float z = g_z[m*Hsz + n], hp = g_h[m*Hsz + n];
                    g_h[m*Hsz + n] = z*hp + (1.f - z)*hh;
                }
            }
        }
    }
}

// ---------------------------------------------------------------------------
// Per-row (b) softmax + double-softmax CE + argmax feedback.
// preds = softmax(logits); ce = logsumexp(preds) - preds[tgt]; tok = argmax.
// Deterministic: each block owns its row's g_ce[b].
// ---------------------------------------------------------------------------
__global__ void softmax_loss_kernel(const int* __restrict__ targ, int tcol)
{
    __shared__ float s_f[256];
    __shared__ int   s_i[256];
    int b = blockIdx.x, tid = threadIdx.x;
    const float* row = g_logits + (size_t)b * Vsz;

    // pass 1: max + first-occurrence argmax
    float bv = -1e30f; int bi = 0;
    for (int n = tid; n < Vsz; n += 256) {
        float l = row[n];
        if (l > bv) { bv = l; bi = n; }
    }
    s_f[tid] = bv; s_i[tid] = bi;
    __syncthreads();
    for (int st = 128; st > 0; st >>= 1) {
        if (tid < st) {
            float v2 = s_f[tid+st]; int i2 = s_i[tid+st];
            if (v2 > s_f[tid] || (v2 == s_f[tid] && i2 < s_i[tid])) {
                s_f[tid] = v2; s_i[tid] = i2;
            }
        }
        __syncthreads();
    }
    float M = s_f[0]; int amax = s_i[0];
    __syncthreads();

    // pass 2: Z = sum exp(l - M)
    float Z = 0.f;
    for (int n = tid; n < Vsz; n += 256) Z += expf(row[n] - M);
    s_f[tid] = Z; __syncthreads();
    for (int st = 128; st > 0; st >>= 1) {
        if (tid < st) s_f[tid] += s_f[tid+st];
        __syncthreads();
    }
    float Zt = s_f[0];
    __syncthreads();

    // pass 3: S2 = sum exp(preds)
    float S2 = 0.f;
    for (int n = tid; n < Vsz; n += 256) S2 += expf(expf(row[n] - M) / Zt);
    s_f[tid] = S2; __syncthreads();
    for (int st = 128; st > 0; st >>= 1) {
        if (tid < st) s_f[tid] += s_f[tid+st];
        __syncthreads();
    }

    if (tid == 0) {
        int tg = targ[b*Tsz + tcol];
        float pt = expf(row[tg] - M) / Zt;
        float ce = logf(s_f[0]) - pt;          // lse(preds) - preds[tgt]
        if (tg != 0) g_ce[b] += ce;
        g_tok[b] = amax;
    }
}

__global__ void final_kernel(float* __restrict__ out)
{
    __shared__ float s[64];
    int tid = threadIdx.x;
    s[tid] = g_ce[tid];
    __syncthreads();
    for (int st = 32; st > 0; st >>= 1) {
        if (tid < st) s[tid] += s[tid+st];
        __syncthreads();
    }
    if (tid == 0) out[0] = s[0] * (1.0f / 64.0f);
}

// ---------------------------------------------------------------------------
extern "C" void kernel_launch(void* const* d_in, const int* in_sizes, int n_in,
                              void* d_out, int out_size)
{
    const int*   inp     = (const int*)  d_in[0];
    const int*   targ    = (const int*)  d_in[1];
    const float* emb_enc = (const float*)d_in[2];
    const float* enc_Wx  = (const float*)d_in[3];
    const float* enc_Wh  = (const float*)d_in[4];
    const float* enc_b   = (const float*)d_in[5];
    const float* emb_dec = (const float*)d_in[6];
    const float* dec_Wx  = (const float*)d_in[7];
    const float* dec_Wh  = (const float*)d_in[8];
    const float* dec_b   = (const float*)d_in[9];
    const float* fc_W    = (const float*)d_in[10];
    const float* fc_b    = (const float*)d_in[11];
    float* out = (float*)d_out;

    init_kernel<<<1, 256>>>();

    // Encoder input projection for all 64 steps at once:
    // g_gx_enc[b*S+t] = emb_enc[inp[b,t]] @ enc_Wx + enc_b
    {
        dim3 g(G3H/64, (Bsz*Ssz)/64);
        gemm_k<0,64,64,16,4,4><<<g, 256>>>(emb_enc, inp, /*a_kind*/0, Esz,
                                           enc_Wx, G3H, enc_b, /*c_sel*/0, G3H,
                                           0, 0, Esz);
    }

    // Encoder recurrence
    for (int t = 0; t < Ssz; t++) {
        dim3 gz((2*Hsz)/64, Bsz/16);
        gemm_k<1,16,64,32,1,4><<<gz, 256>>>(nullptr, nullptr, 2, Hsz,
                                            enc_Wh, G3H, nullptr, 0, 0,
                                            /*gx_sel*/0, t, Hsz);
        dim3 gh(Hsz/64, Bsz/16);
        gemm_k<2,16,64,32,1,4><<<gh, 256>>>(nullptr, nullptr, 3, Hsz,
                                            enc_Wh + 2*Hsz, G3H, nullptr, 0, 0,
                                            /*gx_sel*/0, t, Hsz);
    }

    // Decoder: greedy loop over targ[:, 1..31]
    for (int s = 0; s < Tsz - 1; s++) {
        // gx = emb_dec[tok] @ dec_Wx + dec_b
        dim3 gg(G3H/64, Bsz/16);
        gemm_k<0,16,64,32,1,4><<<gg, 256>>>(emb_dec, nullptr, /*a_kind*/1, Esz,
                                            dec_Wx, G3H, dec_b, /*c_sel*/1, G3H,
                                            0, 0, Esz);
        dim3 gz((2*Hsz)/64, Bsz/16);
        gemm_k<1,16,64,32,1,4><<<gz, 256>>>(nullptr, nullptr, 2, Hsz,
                                            dec_Wh, G3H, nullptr, 0, 0,
                                            /*gx_sel*/1, 0, Hsz);
        dim3 gh(Hsz/64, Bsz/16);
        gemm_k<2,16,64,32,1,4><<<gh, 256>>>(nullptr, nullptr, 3, Hsz,
                                            dec_Wh + 2*Hsz, G3H, nullptr, 0, 0,
                                            /*gx_sel*/1, 0, Hsz);
        // logits = h @ fc_W + fc_b
        dim3 gf(Vsz/64, Bsz/64);
        gemm_k<0,64,64,16,4,4><<<gf, 256>>>(nullptr, nullptr, /*a_kind*/2, Hsz,
                                            fc_W, Vsz, fc_b, /*c_sel*/2, Vsz,
                                            0, 0, Hsz);
        softmax_loss_kernel<<<Bsz, 256>>>(targ, s + 1);
    }

    final_kernel<<<1, 64>>>(out);
}